// round 1
// baseline (speedup 1.0000x reference)
#include <cuda_runtime.h>
#include <math.h>

#define BB 256
#define TT 512
#define II 256
#define HH 512
#define AA 18
#define KK (HH + II)   // 768: concat [h | x]

#define ROWS 8
#define JT   64
#define KC   64
#define STEP_THREADS 256

// ---------------- scratch (static device globals; no allocation) ----------------
__device__ float g_W[(size_t)KK * HH];            // [k][j] : k<512 -> W_hh[j][k], else W_ih[j][k-512]
__device__ float g_bias[HH];                      // b_ih + b_hh
__device__ float g_h[2][BB * HH];                 // double-buffered hidden state
__device__ float g_hout[(size_t)BB * TT * HH];    // masked hidden outputs (only written where t < len)
__device__ int   g_perm[BB];                      // batch rows sorted by length desc
__device__ int   g_active[TT];                    // active(t) = #{len > t}

// ---------------- prep: counting sort by length (desc) + active counts ----------------
__global__ void prep_sort(const int* __restrict__ lengths) {
    __shared__ int s_len[BB];
    __shared__ int s_hist[TT + 1];
    __shared__ int s_S[TT + 1];     // S[v] = #{len > v}
    __shared__ int s_base[TT + 1];
    int tid = threadIdx.x;          // 512 threads
    if (tid < BB) s_len[tid] = lengths[tid];
    for (int i = tid; i <= TT; i += blockDim.x) s_hist[i] = 0;
    __syncthreads();
    if (tid < BB) atomicAdd(&s_hist[s_len[tid]], 1);
    __syncthreads();
    if (tid == 0) {
        s_S[TT] = 0;
        for (int v = TT - 1; v >= 0; --v) s_S[v] = s_S[v + 1] + s_hist[v + 1];
    }
    __syncthreads();
    for (int i = tid; i <= TT; i += blockDim.x) s_base[i] = s_S[i];
    if (tid < TT) g_active[tid] = s_S[tid];
    __syncthreads();
    if (tid < BB) {
        int pos = atomicAdd(&s_base[s_len[tid]], 1);
        g_perm[pos] = tid;   // sorted desc: prefix of perm is the active set at every t
    }
}

// ---------------- prep: pack W into k-major concat layout, bias, h0 ----------------
__global__ void prep_pack(const float* __restrict__ W_ih, const float* __restrict__ W_hh,
                          const float* __restrict__ b_ih, const float* __restrict__ b_hh,
                          const float* __restrict__ h0) {
    int idx = blockIdx.x * blockDim.x + threadIdx.x;
    int stride = gridDim.x * blockDim.x;
    for (int i = idx; i < KK * HH; i += stride) {
        int k = i / HH, j = i % HH;
        g_W[i] = (k < HH) ? W_hh[(size_t)j * HH + k] : W_ih[(size_t)j * II + (k - HH)];
    }
    for (int i = idx; i < HH; i += stride) g_bias[i] = b_ih[i] + b_hh[i];
    for (int i = idx; i < BB * HH; i += stride) g_h[0][i] = h0[i];
}

// ---------------- one recurrence step: h_new = tanh([h|x] @ Wcat + bias) ----------------
// grid: (HH/JT = 8, BB/ROWS = 32), 256 threads
__global__ __launch_bounds__(STEP_THREADS) void step_kernel(const float* __restrict__ x, int t) {
    int active = g_active[t];
    int r0 = blockIdx.y * ROWS;
    if (r0 >= active) return;
    int nrows = min(ROWS, active - r0);
    int j0 = blockIdx.x * JT;
    int buf = t & 1, nb = buf ^ 1;

    __shared__ float s_hx[ROWS][KK];     // 24 KB
    __shared__ float s_w[KC][JT];        // 16 KB
    __shared__ int   s_rowb[ROWS];

    int tid = threadIdx.x;
    if (tid < ROWS) s_rowb[tid] = (tid < nrows) ? g_perm[r0 + tid] : -1;
    __syncthreads();

    // stage [h | x] rows: warp w loads row w
    {
        int rr = tid >> 5, lane = tid & 31;
        int b = s_rowb[rr];
        const float4* hsrc = (b >= 0) ? (const float4*)&g_h[buf][(size_t)b * HH] : nullptr;
        const float4* xsrc = (b >= 0) ? (const float4*)&x[((size_t)b * TT + t) * II] : nullptr;
        float4* dst = (float4*)&s_hx[rr][0];
        #pragma unroll
        for (int c = lane; c < KK / 4; c += 32) {
            float4 v;
            if (b < 0) { v.x = v.y = v.z = v.w = 0.f; }
            else v = (c < HH / 4) ? hsrc[c] : xsrc[c - HH / 4];
            dst[c] = v;
        }
    }

    float a00 = 0.f, a01 = 0.f, a10 = 0.f, a11 = 0.f;
    int jc = (tid & 31) * 2;   // j pair within tile
    int r  = tid >> 5;         // row (uniform per warp -> smem broadcast for h)

    #pragma unroll 1
    for (int kc = 0; kc < KK; kc += KC) {
        __syncthreads();   // hx ready (first iter) / s_w consumed (later iters)
        // stage W chunk [KC x JT] = 1024 float4 by 256 threads
        {
            const float* gw = &g_W[(size_t)kc * HH + j0];
            #pragma unroll
            for (int q = 0; q < (KC * JT) / (STEP_THREADS * 4); ++q) {
                int p  = tid + q * STEP_THREADS;     // float4 index
                int kk = p / (JT / 4);
                int jj = (p % (JT / 4)) * 4;
                *(float4*)&s_w[kk][jj] = *(const float4*)&gw[(size_t)kk * HH + jj];
            }
        }
        __syncthreads();
        const float4* hp = (const float4*)&s_hx[r][kc];
        #pragma unroll
        for (int k4 = 0; k4 < KC / 4; ++k4) {
            float4 h = hp[k4];
            float2 w0 = *(float2*)&s_w[k4 * 4 + 0][jc];
            float2 w1 = *(float2*)&s_w[k4 * 4 + 1][jc];
            float2 w2 = *(float2*)&s_w[k4 * 4 + 2][jc];
            float2 w3 = *(float2*)&s_w[k4 * 4 + 3][jc];
            a00 = fmaf(h.x, w0.x, a00); a01 = fmaf(h.x, w0.y, a01);
            a10 = fmaf(h.y, w1.x, a10); a11 = fmaf(h.y, w1.y, a11);
            a00 = fmaf(h.z, w2.x, a00); a01 = fmaf(h.z, w2.y, a01);
            a10 = fmaf(h.w, w3.x, a10); a11 = fmaf(h.w, w3.y, a11);
        }
    }

    if (r < nrows) {
        int b = s_rowb[r];
        int j = j0 + jc;
        float v0 = tanhf(a00 + a10 + g_bias[j]);
        float v1 = tanhf(a01 + a11 + g_bias[j + 1]);
        float2 vv = make_float2(v0, v1);
        *(float2*)&g_h[nb][(size_t)b * HH + j] = vv;
        *(float2*)&g_hout[((size_t)b * TT + t) * HH + j] = vv;
    }
}

// ---------------- FC head: out[b,t,:] = W_fc @ hout + b_fc (or b_fc past length) ----------------
__global__ __launch_bounds__(256) void fc_kernel(const int* __restrict__ lengths,
                                                 const float* __restrict__ W_fc,
                                                 const float* __restrict__ b_fc,
                                                 float* __restrict__ out,
                                                 int write_len_tail) {
    __shared__ float s_w[AA][HH];   // 36 KB
    __shared__ float s_b[AA];
    int tid = threadIdx.x;
    for (int i = tid; i < AA * HH; i += 256) s_w[i / HH][i % HH] = W_fc[i];
    if (tid < AA) s_b[tid] = b_fc[tid];
    __syncthreads();

    int lane = tid & 31, wid = tid >> 5;
    int gw = blockIdx.x * 8 + wid;
    int nw = gridDim.x * 8;
    float myb = s_b[lane < AA ? lane : 0];

    for (int item = gw; item < BB * TT; item += nw) {
        int b = item / TT, t = item % TT;
        int len = __ldg(&lengths[b]);
        float res;
        if (t < len) {
            const float4* hp = (const float4*)&g_hout[(size_t)item * HH];
            float4 h[4];
            #pragma unroll
            for (int q = 0; q < 4; ++q) h[q] = hp[q * 32 + lane];   // conflict-free, coalesced
            float myval = 0.f;
            #pragma unroll
            for (int a = 0; a < AA; ++a) {
                const float4* wp = (const float4*)&s_w[a][0];
                float p = 0.f;
                #pragma unroll
                for (int q = 0; q < 4; ++q) {
                    float4 w = wp[q * 32 + lane];
                    p = fmaf(h[q].x, w.x, p); p = fmaf(h[q].y, w.y, p);
                    p = fmaf(h[q].z, w.z, p); p = fmaf(h[q].w, w.w, p);
                }
                p += __shfl_xor_sync(0xFFFFFFFFu, p, 16);
                p += __shfl_xor_sync(0xFFFFFFFFu, p, 8);
                p += __shfl_xor_sync(0xFFFFFFFFu, p, 4);
                p += __shfl_xor_sync(0xFFFFFFFFu, p, 2);
                p += __shfl_xor_sync(0xFFFFFFFFu, p, 1);
                if (lane == a) myval = p;
            }
            res = myval + myb;
        } else {
            res = myb;   // reference: zero hidden past length -> action = b_fc
        }
        if (lane < AA) out[(size_t)item * AA + lane] = res;
    }

    if (write_len_tail && blockIdx.x == 0 && tid < BB) {
        out[(size_t)BB * TT * AA + tid] = (float)__ldg(&lengths[tid]);
    }
}

// ---------------- launch ----------------
extern "C" void kernel_launch(void* const* d_in, const int* in_sizes, int n_in,
                              void* d_out, int out_size) {
    const float* x      = (const float*)d_in[0];
    const float* h0     = (const float*)d_in[1];
    const int*   lengths= (const int*)  d_in[2];
    const float* W_ih   = (const float*)d_in[3];
    const float* W_hh   = (const float*)d_in[4];
    const float* b_ih   = (const float*)d_in[5];
    const float* b_hh   = (const float*)d_in[6];
    const float* W_fc   = (const float*)d_in[7];
    const float* b_fc   = (const float*)d_in[8];
    float* out = (float*)d_out;

    prep_sort<<<1, 512>>>(lengths);
    prep_pack<<<512, 256>>>(W_ih, W_hh, b_ih, b_hh, h0);

    for (int t = 0; t < TT; ++t) {
        step_kernel<<<dim3(HH / JT, BB / ROWS), STEP_THREADS>>>(x, t);
    }

    int tail = (out_size >= BB * TT * AA + BB) ? 1 : 0;
    fc_kernel<<<512, 256>>>(lengths, W_fc, b_fc, out, tail);
}